// round 1
// baseline (speedup 1.0000x reference)
#include <cuda_runtime.h>
#include <math.h>

#define B      8
#define DIM    64
#define HEADS  2
#define CH     32      // channels per head
#define HH     256
#define WW     256
#define NPIX   65536   // HH*WW
#define QKVC   192     // 3*DIM

// ---------------- scratch (device globals; no allocation allowed) -----------
__device__ float g_mid[(size_t)B * QKVC * NPIX];   // qkv after 1x1 conv
__device__ float g_qkv[(size_t)B * QKVC * NPIX];   // qkv after depthwise conv
__device__ float g_gram[B * HEADS * CH * CH];      // unnormalized q@k^T
__device__ float g_sqn[B * 2 * DIM];               // sum of squares: q (0..63), k (64..127) per batch
__device__ float g_A[B * HEADS * CH * CH];         // combined attention
__device__ float g_M[B * DIM * DIM];               // W_proj @ blockdiag(A)

// ---------------- kernel 0: zero the atomic accumulators --------------------
__global__ void k_zero() {
    int t = blockIdx.x * blockDim.x + threadIdx.x;
    if (t < B * HEADS * CH * CH) g_gram[t] = 0.f;
    if (t < B * 2 * DIM)         g_sqn[t]  = 0.f;
}

// ---------------- kernel 1: 1x1 conv (x [b,64,N] -> g_mid [b,192,N]) --------
// Block: 128 pixels, all 192 output channels. 16x16 threads, 12x8 register tile.
__global__ __launch_bounds__(256) void k_conv1(const float* __restrict__ x,
                                               const float* __restrict__ wqkv) {
    extern __shared__ float sm[];
    float* ws = sm;              // [64][192]  ws[k][oc]
    float* xs = sm + 64 * QKVC;  // [64][128]  xs[ic][px]

    const int b  = blockIdx.y;
    const long n0 = (long)blockIdx.x * 128;
    const int tx = threadIdx.x, ty = threadIdx.y;
    const int tid = ty * 16 + tx;

    for (int idx = tid; idx < QKVC * 64; idx += 256) {
        int oc = idx >> 6, k = idx & 63;
        ws[k * QKVC + oc] = wqkv[idx];                 // wqkv[oc][ic]
    }
    const float* xb = x + (size_t)b * DIM * NPIX + n0;
    for (int idx = tid; idx < 64 * 128; idx += 256) {
        int ic = idx >> 7, px = idx & 127;
        xs[ic * 128 + px] = xb[(size_t)ic * NPIX + px];
    }
    __syncthreads();

    float acc[12][8];
#pragma unroll
    for (int i = 0; i < 12; i++)
#pragma unroll
        for (int j = 0; j < 8; j++) acc[i][j] = 0.f;

    const int ocb = ty * 12;
#pragma unroll 4
    for (int k = 0; k < 64; k++) {
        float xr[8];
#pragma unroll
        for (int j = 0; j < 8; j++) xr[j] = xs[k * 128 + tx + 16 * j];
        const float4 w0 = *(const float4*)&ws[k * QKVC + ocb];
        const float4 w1 = *(const float4*)&ws[k * QKVC + ocb + 4];
        const float4 w2 = *(const float4*)&ws[k * QKVC + ocb + 8];
        float wr[12] = {w0.x, w0.y, w0.z, w0.w, w1.x, w1.y, w1.z, w1.w,
                        w2.x, w2.y, w2.z, w2.w};
#pragma unroll
        for (int i = 0; i < 12; i++)
#pragma unroll
            for (int j = 0; j < 8; j++)
                acc[i][j] = fmaf(wr[i], xr[j], acc[i][j]);
    }

    float* ob = g_mid + (size_t)b * QKVC * NPIX + n0;
#pragma unroll
    for (int i = 0; i < 12; i++)
#pragma unroll
        for (int j = 0; j < 8; j++)
            ob[(size_t)(ocb + i) * NPIX + tx + 16 * j] = acc[i][j];
}

// ---------------- kernel 2: depthwise 3x3 conv + fused sq-norm --------------
// grid (8, 32, B*192), block (32, 8): 32x8 pixel tile per channel plane.
__global__ void k_dw(const float* __restrict__ wdw) {
    const int bc = blockIdx.z;           // b*192 + c
    const int c  = bc % QKVC;
    const int b  = bc / QKVC;
    const int x0 = blockIdx.x * 32, y0 = blockIdx.y * 8;

    __shared__ float tile[10][34];
    const float* in = g_mid + (size_t)bc * NPIX;
    const int tid = threadIdx.y * 32 + threadIdx.x;

    for (int idx = tid; idx < 340; idx += 256) {
        int yy = idx / 34, xx = idx % 34;
        int gy = y0 + yy - 1, gx = x0 + xx - 1;
        tile[yy][xx] = (gy >= 0 && gy < HH && gx >= 0 && gx < WW)
                           ? in[gy * WW + gx] : 0.f;
    }
    __syncthreads();

    float w[9];
#pragma unroll
    for (int t = 0; t < 9; t++) w[t] = wdw[c * 9 + t];

    float a = 0.f;
#pragma unroll
    for (int ky = 0; ky < 3; ky++)
#pragma unroll
        for (int kx = 0; kx < 3; kx++)
            a = fmaf(w[ky * 3 + kx], tile[threadIdx.y + ky][threadIdx.x + kx], a);

    g_qkv[(size_t)bc * NPIX + (y0 + threadIdx.y) * WW + x0 + threadIdx.x] = a;

    if (c < 2 * DIM) {  // q or k channel: accumulate sum of squares
        float s = a * a;
#pragma unroll
        for (int o = 16; o; o >>= 1) s += __shfl_down_sync(0xffffffffu, s, o);
        __shared__ float red[8];
        if (threadIdx.x == 0) red[threadIdx.y] = s;
        __syncthreads();
        if (tid == 0) {
            float tot = 0.f;
#pragma unroll
            for (int wv = 0; wv < 8; wv++) tot += red[wv];
            atomicAdd(&g_sqn[b * 2 * DIM + c], tot);
        }
    }
}

// ---------------- kernel 3: Gram matrix G = q @ k^T (unnormalized) ----------
// grid (16 chunks, B*HEADS). Each block: 4096 pixels, full 32x32 output tile.
__global__ __launch_bounds__(256) void k_gram() {
    __shared__ float qs[32][132];
    __shared__ float ks[32][132];

    const int bh = blockIdx.y;
    const int b = bh >> 1, h = bh & 1;
    const long n0 = (long)blockIdx.x * 4096;
    const float* qg = g_qkv + ((size_t)b * QKVC + h * CH) * NPIX + n0;
    const float* kg = g_qkv + ((size_t)b * QKVC + DIM + h * CH) * NPIX + n0;
    const int tid = threadIdx.x;
    const int i0 = (tid >> 4) * 2;
    const int j0 = (tid & 15) * 2;

    float a00 = 0.f, a01 = 0.f, a10 = 0.f, a11 = 0.f;
    for (int s = 0; s < 32; s++) {
        __syncthreads();
        for (int idx = tid; idx < 32 * 32; idx += 256) {
            int r = idx >> 5, pv = idx & 31;
            ((float4*)qs[r])[pv] = ((const float4*)(qg + (size_t)r * NPIX + s * 128))[pv];
            ((float4*)ks[r])[pv] = ((const float4*)(kg + (size_t)r * NPIX + s * 128))[pv];
        }
        __syncthreads();
#pragma unroll 8
        for (int p = 0; p < 128; p += 4) {
            float4 qa = *(float4*)&qs[i0][p];
            float4 qb = *(float4*)&qs[i0 + 1][p];
            float4 ka = *(float4*)&ks[j0][p];
            float4 kb = *(float4*)&ks[j0 + 1][p];
            a00 = fmaf(qa.x, ka.x, fmaf(qa.y, ka.y, fmaf(qa.z, ka.z, fmaf(qa.w, ka.w, a00))));
            a01 = fmaf(qa.x, kb.x, fmaf(qa.y, kb.y, fmaf(qa.z, kb.z, fmaf(qa.w, kb.w, a01))));
            a10 = fmaf(qb.x, ka.x, fmaf(qb.y, ka.y, fmaf(qb.z, ka.z, fmaf(qb.w, ka.w, a10))));
            a11 = fmaf(qb.x, kb.x, fmaf(qb.y, kb.y, fmaf(qb.z, kb.z, fmaf(qb.w, kb.w, a11))));
        }
    }
    float* G = g_gram + bh * CH * CH;
    atomicAdd(&G[i0 * CH + j0],           a00);
    atomicAdd(&G[i0 * CH + j0 + 1],       a01);
    atomicAdd(&G[(i0 + 1) * CH + j0],     a10);
    atomicAdd(&G[(i0 + 1) * CH + j0 + 1], a11);
}

// ---------------- kernel 4: normalize, triple top-k softmax, combine --------
// grid (B*HEADS), 32 threads; thread i owns row i of the 32x32 attention.
__global__ void k_comb(const float* __restrict__ temp, const float* __restrict__ a1,
                       const float* __restrict__ a2, const float* __restrict__ a3) {
    const int bh = blockIdx.x;
    const int b = bh >> 1, h = bh & 1;
    const int i = threadIdx.x;

    __shared__ float nks[CH];
    float nq = fmaxf(sqrtf(g_sqn[b * 2 * DIM + h * CH + i]), 1e-12f);
    float nk = fmaxf(sqrtf(g_sqn[b * 2 * DIM + DIM + h * CH + i]), 1e-12f);
    nks[i] = nk;
    __syncthreads();

    const float t = temp[h];
    float v[CH];
#pragma unroll
    for (int j = 0; j < CH; j++)
        v[j] = g_gram[bh * CH * CH + i * CH + j] / nq * t / nks[j];

    // rank = #{l : v_l > v_j} + #{l<j : v_l == v_j}  (matches lax.top_k ties)
    int rank[CH];
#pragma unroll
    for (int j = 0; j < CH; j++) {
        int r = 0;
        float vj = v[j];
#pragma unroll
        for (int l = 0; l < CH; l++)
            r += (v[l] > vj) || (v[l] == vj && l < j);
        rank[j] = r;
    }

    float mx = -1e30f;
#pragma unroll
    for (int j = 0; j < CH; j++) mx = fmaxf(mx, v[j]);

    float e[CH], s16 = 0.f, s21 = 0.f, s24 = 0.f;
#pragma unroll
    for (int j = 0; j < CH; j++) {
        float ev = expf(v[j] - mx);
        e[j] = ev;
        if (rank[j] < 16) s16 += ev;
        if (rank[j] < 21) s21 += ev;
        if (rank[j] < 24) s24 += ev;
    }
    const float w1 = a1[0] / s16, w2 = a2[0] / s21, w3 = a3[0] / s24;
#pragma unroll
    for (int j = 0; j < CH; j++) {
        float coef = (rank[j] < 16 ? w1 : 0.f) + (rank[j] < 21 ? w2 : 0.f)
                   + (rank[j] < 24 ? w3 : 0.f);
        g_A[bh * CH * CH + i * CH + j] = e[j] * coef;
    }
}

// ---------------- kernel 5: M[b] = W_proj @ blockdiag(A[b,0], A[b,1]) -------
__global__ void k_buildM(const float* __restrict__ wproj) {
    const int b = blockIdx.x;
    __shared__ float As[HEADS * CH * CH];  // 2048
    __shared__ float Ws[DIM * DIM];        // 4096
    const int tid = threadIdx.x;           // 128 threads
    for (int idx = tid; idx < HEADS * CH * CH; idx += 128) As[idx] = g_A[b * HEADS * CH * CH + idx];
    for (int idx = tid; idx < DIM * DIM; idx += 128)       Ws[idx] = wproj[idx];
    __syncthreads();

#pragma unroll
    for (int m = 0; m < 32; m++) {
        int idx = tid + 128 * m;
        int o = idx >> 6, ci = idx & 63;
        int h = ci >> 5, cj = ci & 31;
        float s = 0.f;
#pragma unroll
        for (int cp = 0; cp < CH; cp++)
            s = fmaf(Ws[o * DIM + h * CH + cp], As[h * CH * CH + cp * CH + cj], s);
        g_M[b * DIM * DIM + idx] = s;
    }
}

// ---------------- kernel 6: out = M[b] @ v, write final output --------------
__global__ __launch_bounds__(256) void k_out(float* __restrict__ out) {
    extern __shared__ float sm[];
    float* ms = sm;             // [64][64]  ms[ci][o]  (transposed M)
    float* vs = sm + DIM * DIM; // [64][128] vs[ci][px]

    const int b = blockIdx.y;
    const long n0 = (long)blockIdx.x * 128;
    const int tx = threadIdx.x, ty = threadIdx.y;
    const int tid = ty * 16 + tx;

    const float* Mb = g_M + b * DIM * DIM;
    for (int idx = tid; idx < DIM * DIM; idx += 256) {
        int o = idx >> 6, ci = idx & 63;
        ms[ci * DIM + o] = Mb[idx];
    }
    const float* vg = g_qkv + ((size_t)b * QKVC + 2 * DIM) * NPIX + n0;
    for (int idx = tid; idx < 64 * 128; idx += 256) {
        int ci = idx >> 7, px = idx & 127;
        vs[ci * 128 + px] = vg[(size_t)ci * NPIX + px];
    }
    __syncthreads();

    float acc[4][8];
#pragma unroll
    for (int i = 0; i < 4; i++)
#pragma unroll
        for (int j = 0; j < 8; j++) acc[i][j] = 0.f;

    const int ob4 = ty * 4;
#pragma unroll 4
    for (int ci = 0; ci < 64; ci++) {
        float4 w = *(float4*)&ms[ci * DIM + ob4];
        float wr[4] = {w.x, w.y, w.z, w.w};
        float xr[8];
#pragma unroll
        for (int j = 0; j < 8; j++) xr[j] = vs[ci * 128 + tx + 16 * j];
#pragma unroll
        for (int i = 0; i < 4; i++)
#pragma unroll
            for (int j = 0; j < 8; j++)
                acc[i][j] = fmaf(wr[i], xr[j], acc[i][j]);
    }

    float* ob = out + (size_t)b * DIM * NPIX + n0;
#pragma unroll
    for (int i = 0; i < 4; i++)
#pragma unroll
        for (int j = 0; j < 8; j++)
            ob[(size_t)(ob4 + i) * NPIX + tx + 16 * j] = acc[i][j];
}

// ---------------- launcher ---------------------------------------------------
extern "C" void kernel_launch(void* const* d_in, const int* in_sizes, int n_in,
                              void* d_out, int out_size) {
    const float* x     = (const float*)d_in[0];
    const float* wqkv  = (const float*)d_in[1];
    const float* wdw   = (const float*)d_in[2];
    const float* wproj = (const float*)d_in[3];
    const float* temp  = (const float*)d_in[4];
    const float* a1    = (const float*)d_in[5];
    const float* a2    = (const float*)d_in[6];
    const float* a3    = (const float*)d_in[7];
    float* out = (float*)d_out;

    cudaFuncSetAttribute(k_conv1, cudaFuncAttributeMaxDynamicSharedMemorySize, 81920);
    cudaFuncSetAttribute(k_out,   cudaFuncAttributeMaxDynamicSharedMemorySize, 49152);

    k_zero<<<64, 256>>>();
    k_conv1<<<dim3(512, 8), dim3(16, 16), 81920>>>(x, wqkv);
    k_dw<<<dim3(8, 32, B * QKVC), dim3(32, 8)>>>(wdw);
    k_gram<<<dim3(16, 16), 256>>>();
    k_comb<<<16, 32>>>(temp, a1, a2, a3);
    k_buildM<<<8, 128>>>(wproj);
    k_out<<<dim3(512, 8), dim3(16, 16), 49152>>>(out);
}

// round 2
// speedup vs baseline: 1.1908x; 1.1908x over previous
#include <cuda_runtime.h>
#include <math.h>

#define B      8
#define DIM    64
#define HEADS  2
#define CH     32      // channels per head
#define HH     256
#define WW     256
#define NPIX   65536   // HH*WW
#define QKVC   192     // 3*DIM

// ---------------- packed f32x2 helpers (bit-exact vs scalar fp32 FMA) -------
typedef unsigned long long u64;
__device__ __forceinline__ void fma2(u64& d, u64 a, u64 b, u64 c) {
    asm("fma.rn.f32x2 %0,%1,%2,%3;" : "=l"(d) : "l"(a), "l"(b), "l"(c));
}
__device__ __forceinline__ u64 pk2(float lo, float hi) {
    u64 r; asm("mov.b64 %0,{%1,%2};" : "=l"(r) : "f"(lo), "f"(hi)); return r;
}
__device__ __forceinline__ float2 upk2(u64 v) {
    float2 r; asm("mov.b64 {%0,%1},%2;" : "=f"(r.x), "=f"(r.y) : "l"(v)); return r;
}

// ---------------- scratch (device globals; no allocation allowed) -----------
__device__ float g_mid[(size_t)B * QKVC * NPIX];   // qkv after 1x1 conv
__device__ float g_qkv[(size_t)B * QKVC * NPIX];   // qkv after depthwise conv
__device__ float g_gram[B * HEADS * CH * CH];      // unnormalized q@k^T
__device__ float g_sqn[B * 2 * DIM];               // sum sq: q (0..63), k (64..127)
__device__ float g_A[B * HEADS * CH * CH];         // combined attention
__device__ float g_M[B * DIM * DIM];               // W_proj @ blockdiag(A)

// ---------------- kernel 0: zero the atomic accumulators --------------------
__global__ void k_zero() {
    int t = blockIdx.x * blockDim.x + threadIdx.x;
    if (t < B * HEADS * CH * CH) g_gram[t] = 0.f;
    if (t < B * 2 * DIM)         g_sqn[t]  = 0.f;
}

// ---------------- kernel 1: 1x1 conv, f32x2 packed over oc pairs ------------
// Block: 128 pixels, all 192 output channels. 16x16 threads.
// Thread: 12 oc (6 packed pairs) x 8 pixels.
__global__ __launch_bounds__(256) void k_conv1(const float* __restrict__ x,
                                               const float* __restrict__ wqkv) {
    extern __shared__ float sm[];
    float* ws = sm;              // [64][192]  ws[k][oc]
    float* xs = sm + 64 * QKVC;  // [64][128]  xs[ic][px]

    const int b  = blockIdx.y;
    const long n0 = (long)blockIdx.x * 128;
    const int tx = threadIdx.x, ty = threadIdx.y;
    const int tid = ty * 16 + tx;

    for (int idx = tid; idx < QKVC * 64; idx += 256) {
        int oc = idx >> 6, k = idx & 63;
        ws[k * QKVC + oc] = wqkv[idx];                 // wqkv[oc][ic]
    }
    const float* xb = x + (size_t)b * DIM * NPIX + n0;
    for (int idx = tid; idx < 64 * 32; idx += 256) {
        int ic = idx >> 5, pv = idx & 31;
        ((float4*)&xs[ic * 128])[pv] = ((const float4*)(xb + (size_t)ic * NPIX))[pv];
    }
    __syncthreads();

    u64 acc[6][8];
#pragma unroll
    for (int p = 0; p < 6; p++)
#pragma unroll
        for (int j = 0; j < 8; j++) acc[p][j] = 0ull;

    const int ocb = ty * 12;
#pragma unroll 4
    for (int k = 0; k < 64; k++) {
        // 6 oc-pairs: reinterpret shared weight row (ocb*4 = 48*ty, 16B aligned)
        const ulonglong2* wp = (const ulonglong2*)(ws + k * QKVC + ocb);
        ulonglong2 wA = wp[0], wB = wp[1], wC = wp[2];
        u64 wr[6] = {wA.x, wA.y, wB.x, wB.y, wC.x, wC.y};
        u64 xd[8];
#pragma unroll
        for (int j = 0; j < 8; j++) {
            float xv = xs[k * 128 + tx + 16 * j];
            xd[j] = pk2(xv, xv);
        }
#pragma unroll
        for (int p = 0; p < 6; p++)
#pragma unroll
            for (int j = 0; j < 8; j++)
                fma2(acc[p][j], wr[p], xd[j], acc[p][j]);
    }

    float* ob = g_mid + (size_t)b * QKVC * NPIX + n0;
#pragma unroll
    for (int p = 0; p < 6; p++)
#pragma unroll
        for (int j = 0; j < 8; j++) {
            float2 r = upk2(acc[p][j]);
            ob[(size_t)(ocb + 2 * p) * NPIX + tx + 16 * j]     = r.x;
            ob[(size_t)(ocb + 2 * p + 1) * NPIX + tx + 16 * j] = r.y;
        }
}

// ---------------- kernel 2: depthwise 3x3 conv + fused sq-norm --------------
// grid (8, 16, B*192), block (32, 8): 32x16 pixel tile, 2 pixels/thread.
__global__ void k_dw(const float* __restrict__ wdw) {
    const int bc = blockIdx.z;           // b*192 + c
    const int c  = bc % QKVC;
    const int b  = bc / QKVC;
    const int x0 = blockIdx.x * 32, y0 = blockIdx.y * 16;

    __shared__ float tile[18][34];
    const float* in = g_mid + (size_t)bc * NPIX;
    const int tid = threadIdx.y * 32 + threadIdx.x;

    for (int idx = tid; idx < 612; idx += 256) {
        int yy = idx / 34, xx = idx % 34;
        int gy = y0 + yy - 1, gx = x0 + xx - 1;
        tile[yy][xx] = (gy >= 0 && gy < HH && gx >= 0 && gx < WW)
                           ? in[gy * WW + gx] : 0.f;
    }
    __syncthreads();

    float w[9];
#pragma unroll
    for (int t = 0; t < 9; t++) w[t] = wdw[c * 9 + t];

    float sq = 0.f;
    float* outp = g_qkv + (size_t)bc * NPIX + x0 + threadIdx.x;
#pragma unroll
    for (int half = 0; half < 2; half++) {
        const int ly = threadIdx.y + half * 8;
        float a = 0.f;
#pragma unroll
        for (int ky = 0; ky < 3; ky++)
#pragma unroll
            for (int kx = 0; kx < 3; kx++)
                a = fmaf(w[ky * 3 + kx], tile[ly + ky][threadIdx.x + kx], a);
        outp[(size_t)(y0 + ly) * WW] = a;
        sq = fmaf(a, a, sq);
    }

    if (c < 2 * DIM) {  // q or k channel: accumulate sum of squares
        float s = sq;
#pragma unroll
        for (int o = 16; o; o >>= 1) s += __shfl_down_sync(0xffffffffu, s, o);
        __shared__ float red[8];
        if (threadIdx.x == 0) red[threadIdx.y] = s;
        __syncthreads();
        if (tid == 0) {
            float tot = 0.f;
#pragma unroll
            for (int wv = 0; wv < 8; wv++) tot += red[wv];
            atomicAdd(&g_sqn[b * 2 * DIM + c], tot);
        }
    }
}

// ---------------- kernel 3: Gram matrix G = q @ k^T (unnormalized) ----------
// grid (64 chunks, B*HEADS). Each block: 1024 pixels, full 32x32 output tile.
__global__ __launch_bounds__(256) void k_gram() {
    __shared__ float qs[32][132];
    __shared__ float ks[32][132];

    const int bh = blockIdx.y;
    const int b = bh >> 1, h = bh & 1;
    const long n0 = (long)blockIdx.x * 1024;
    const float* qg = g_qkv + ((size_t)b * QKVC + h * CH) * NPIX + n0;
    const float* kg = g_qkv + ((size_t)b * QKVC + DIM + h * CH) * NPIX + n0;
    const int tid = threadIdx.x;
    const int i0 = (tid >> 4) * 2;
    const int j0 = (tid & 15) * 2;

    float a00 = 0.f, a01 = 0.f, a10 = 0.f, a11 = 0.f;
    for (int s = 0; s < 8; s++) {
        __syncthreads();
        for (int idx = tid; idx < 32 * 32; idx += 256) {
            int r = idx >> 5, pv = idx & 31;
            ((float4*)qs[r])[pv] = ((const float4*)(qg + (size_t)r * NPIX + s * 128))[pv];
            ((float4*)ks[r])[pv] = ((const float4*)(kg + (size_t)r * NPIX + s * 128))[pv];
        }
        __syncthreads();
#pragma unroll 8
        for (int p = 0; p < 128; p += 4) {
            float4 qa = *(float4*)&qs[i0][p];
            float4 qb = *(float4*)&qs[i0 + 1][p];
            float4 ka = *(float4*)&ks[j0][p];
            float4 kb = *(float4*)&ks[j0 + 1][p];
            a00 = fmaf(qa.x, ka.x, fmaf(qa.y, ka.y, fmaf(qa.z, ka.z, fmaf(qa.w, ka.w, a00))));
            a01 = fmaf(qa.x, kb.x, fmaf(qa.y, kb.y, fmaf(qa.z, kb.z, fmaf(qa.w, kb.w, a01))));
            a10 = fmaf(qb.x, ka.x, fmaf(qb.y, ka.y, fmaf(qb.z, ka.z, fmaf(qb.w, ka.w, a10))));
            a11 = fmaf(qb.x, kb.x, fmaf(qb.y, kb.y, fmaf(qb.z, kb.z, fmaf(qb.w, kb.w, a11))));
        }
    }
    float* G = g_gram + bh * CH * CH;
    atomicAdd(&G[i0 * CH + j0],           a00);
    atomicAdd(&G[i0 * CH + j0 + 1],       a01);
    atomicAdd(&G[(i0 + 1) * CH + j0],     a10);
    atomicAdd(&G[(i0 + 1) * CH + j0 + 1], a11);
}

// ---------------- kernel 4: normalize, triple top-k softmax, combine --------
__global__ void k_comb(const float* __restrict__ temp, const float* __restrict__ a1,
                       const float* __restrict__ a2, const float* __restrict__ a3) {
    const int bh = blockIdx.x;
    const int b = bh >> 1, h = bh & 1;
    const int i = threadIdx.x;

    __shared__ float nks[CH];
    float nq = fmaxf(sqrtf(g_sqn[b * 2 * DIM + h * CH + i]), 1e-12f);
    float nk = fmaxf(sqrtf(g_sqn[b * 2 * DIM + DIM + h * CH + i]), 1e-12f);
    nks[i] = nk;
    __syncthreads();

    const float t = temp[h];
    float v[CH];
#pragma unroll
    for (int j = 0; j < CH; j++)
        v[j] = g_gram[bh * CH * CH + i * CH + j] / nq * t / nks[j];

    int rank[CH];
#pragma unroll
    for (int j = 0; j < CH; j++) {
        int r = 0;
        float vj = v[j];
#pragma unroll
        for (int l = 0; l < CH; l++)
            r += (v[l] > vj) || (v[l] == vj && l < j);
        rank[j] = r;
    }

    float mx = -1e30f;
#pragma unroll
    for (int j = 0; j < CH; j++) mx = fmaxf(mx, v[j]);

    float e[CH], s16 = 0.f, s21 = 0.f, s24 = 0.f;
#pragma unroll
    for (int j = 0; j < CH; j++) {
        float ev = expf(v[j] - mx);
        e[j] = ev;
        if (rank[j] < 16) s16 += ev;
        if (rank[j] < 21) s21 += ev;
        if (rank[j] < 24) s24 += ev;
    }
    const float w1 = a1[0] / s16, w2 = a2[0] / s21, w3 = a3[0] / s24;
#pragma unroll
    for (int j = 0; j < CH; j++) {
        float coef = (rank[j] < 16 ? w1 : 0.f) + (rank[j] < 21 ? w2 : 0.f)
                   + (rank[j] < 24 ? w3 : 0.f);
        g_A[bh * CH * CH + i * CH + j] = e[j] * coef;
    }
}

// ---------------- kernel 5: M[b] = W_proj @ blockdiag(A[b,0], A[b,1]) -------
__global__ void k_buildM(const float* __restrict__ wproj) {
    const int b = blockIdx.x;
    __shared__ float As[HEADS * CH * CH];  // 2048
    __shared__ float Ws[DIM * DIM];        // 4096
    const int tid = threadIdx.x;           // 128 threads
    for (int idx = tid; idx < HEADS * CH * CH; idx += 128) As[idx] = g_A[b * HEADS * CH * CH + idx];
    for (int idx = tid; idx < DIM * DIM; idx += 128)       Ws[idx] = wproj[idx];
    __syncthreads();

#pragma unroll
    for (int m = 0; m < 32; m++) {
        int idx = tid + 128 * m;
        int o = idx >> 6, ci = idx & 63;
        int h = ci >> 5, cj = ci & 31;
        float s = 0.f;
#pragma unroll
        for (int cp = 0; cp < CH; cp++)
            s = fmaf(Ws[o * DIM + h * CH + cp], As[h * CH * CH + cp * CH + cj], s);
        g_M[b * DIM * DIM + idx] = s;
    }
}

// ---------------- kernel 6: out = M[b] @ v, f32x2 packed over pixel pairs ---
// Block: 256 pixels, 64 oc. 16x16 threads; thread: 4 oc x 8 pixel-pairs.
__global__ __launch_bounds__(256) void k_out(float* __restrict__ out) {
    extern __shared__ float sm[];
    float* ms = sm;             // [64][64]  ms[ci][o]  (transposed M)
    float* vs = sm + DIM * DIM; // [64][256] vs[ci][px]

    const int b = blockIdx.y;
    const long n0 = (long)blockIdx.x * 256;
    const int tx = threadIdx.x, ty = threadIdx.y;
    const int tid = ty * 16 + tx;

    const float* Mb = g_M + b * DIM * DIM;
    for (int idx = tid; idx < DIM * DIM; idx += 256) {
        int o = idx >> 6, ci = idx & 63;
        ms[ci * DIM + o] = Mb[idx];
    }
    const float* vg = g_qkv + ((size_t)b * QKVC + 2 * DIM) * NPIX + n0;
    for (int idx = tid; idx < 64 * 64; idx += 256) {
        int ci = idx >> 6, pv = idx & 63;
        ((float4*)&vs[ci * 256])[pv] = ((const float4*)(vg + (size_t)ci * NPIX))[pv];
    }
    __syncthreads();

    u64 acc[4][8];
#pragma unroll
    for (int i = 0; i < 4; i++)
#pragma unroll
        for (int j = 0; j < 8; j++) acc[i][j] = 0ull;

    const int ob4 = ty * 4;
#pragma unroll 4
    for (int ci = 0; ci < 64; ci++) {
        float4 w = *(float4*)&ms[ci * DIM + ob4];
        u64 wd[4] = {pk2(w.x, w.x), pk2(w.y, w.y), pk2(w.z, w.z), pk2(w.w, w.w)};
        // 8 natural pixel pairs per thread: pair j covers pixels 2*(tx+16j), +1
        u64 xp[8];
#pragma unroll
        for (int j = 0; j < 8; j++)
            xp[j] = *(const u64*)&vs[ci * 256 + 2 * (tx + 16 * j)];
#pragma unroll
        for (int i = 0; i < 4; i++)
#pragma unroll
            for (int j = 0; j < 8; j++)
                fma2(acc[i][j], wd[i], xp[j], acc[i][j]);
    }

    float* ob = out + (size_t)b * DIM * NPIX + n0;
#pragma unroll
    for (int i = 0; i < 4; i++)
#pragma unroll
        for (int j = 0; j < 8; j++) {
            float2 r = upk2(acc[i][j]);
            *(float2*)&ob[(size_t)(ob4 + i) * NPIX + 2 * (tx + 16 * j)] = r;
        }
}

// ---------------- launcher ---------------------------------------------------
extern "C" void kernel_launch(void* const* d_in, const int* in_sizes, int n_in,
                              void* d_out, int out_size) {
    const float* x     = (const float*)d_in[0];
    const float* wqkv  = (const float*)d_in[1];
    const float* wdw   = (const float*)d_in[2];
    const float* wproj = (const float*)d_in[3];
    const float* temp  = (const float*)d_in[4];
    const float* a1    = (const float*)d_in[5];
    const float* a2    = (const float*)d_in[6];
    const float* a3    = (const float*)d_in[7];
    float* out = (float*)d_out;

    cudaFuncSetAttribute(k_conv1, cudaFuncAttributeMaxDynamicSharedMemorySize, 81920);
    cudaFuncSetAttribute(k_out,   cudaFuncAttributeMaxDynamicSharedMemorySize, 81920);

    k_zero<<<64, 256>>>();
    k_conv1<<<dim3(512, 8), dim3(16, 16), 81920>>>(x, wqkv);
    k_dw<<<dim3(8, 16, B * QKVC), dim3(32, 8)>>>(wdw);
    k_gram<<<dim3(64, 16), 256>>>();
    k_comb<<<16, 32>>>(temp, a1, a2, a3);
    k_buildM<<<8, 128>>>(wproj);
    k_out<<<dim3(256, 8), dim3(16, 16), 81920>>>(out);
}

// round 3
// speedup vs baseline: 1.2384x; 1.0400x over previous
#include <cuda_runtime.h>
#include <math.h>

#define B      8
#define DIM    64
#define HEADS  2
#define CH     32      // channels per head
#define HH     256
#define WW     256
#define NPIX   65536   // HH*WW
#define QKVC   192     // 3*DIM

// ---------------- packed f32x2 helpers (bit-exact vs scalar fp32 FMA) -------
typedef unsigned long long u64;
__device__ __forceinline__ void fma2(u64& d, u64 a, u64 b, u64 c) {
    asm("fma.rn.f32x2 %0,%1,%2,%3;" : "=l"(d) : "l"(a), "l"(b), "l"(c));
}
__device__ __forceinline__ u64 pk2(float lo, float hi) {
    u64 r; asm("mov.b64 %0,{%1,%2};" : "=l"(r) : "f"(lo), "f"(hi)); return r;
}
__device__ __forceinline__ float2 upk2(u64 v) {
    float2 r; asm("mov.b64 {%0,%1},%2;" : "=f"(r.x), "=f"(r.y) : "l"(v)); return r;
}

// ---------------- scratch (device globals; no allocation allowed) -----------
__device__ float g_mid[(size_t)B * QKVC * NPIX];   // qkv after 1x1 conv
__device__ float g_qkv[(size_t)B * QKVC * NPIX];   // qkv after depthwise conv
__device__ float g_gram[B * HEADS * CH * CH];      // unnormalized q@k^T
__device__ float g_sqn[B * 2 * DIM];               // sum sq: q (0..63), k (64..127)
__device__ float g_A[B * HEADS * CH * CH];         // combined attention
__device__ float g_M[B * DIM * DIM];               // W_proj @ blockdiag(A)

// ---------------- kernel 0: zero the atomic accumulators --------------------
__global__ void k_zero() {
    int t = blockIdx.x * blockDim.x + threadIdx.x;
    if (t < B * HEADS * CH * CH) g_gram[t] = 0.f;
    if (t < B * 2 * DIM)         g_sqn[t]  = 0.f;
}

// ---------------- kernel 1: 1x1 conv, f32x2 packed over oc pairs ------------
// Block: 128 pixels, all 192 output channels. 16x16 threads.
// Thread: 12 oc (6 packed pairs) x 8 pixels.
__global__ __launch_bounds__(256) void k_conv1(const float* __restrict__ x,
                                               const float* __restrict__ wqkv) {
    extern __shared__ float sm[];
    float* ws = sm;              // [64][192]  ws[k][oc]
    float* xs = sm + 64 * QKVC;  // [64][128]  xs[ic][px]

    const int b  = blockIdx.y;
    const long n0 = (long)blockIdx.x * 128;
    const int tx = threadIdx.x, ty = threadIdx.y;
    const int tid = ty * 16 + tx;

    for (int idx = tid; idx < QKVC * 64; idx += 256) {
        int oc = idx >> 6, k = idx & 63;
        ws[k * QKVC + oc] = wqkv[idx];                 // wqkv[oc][ic]
    }
    const float* xb = x + (size_t)b * DIM * NPIX + n0;
    for (int idx = tid; idx < 64 * 32; idx += 256) {
        int ic = idx >> 5, pv = idx & 31;
        ((float4*)&xs[ic * 128])[pv] = ((const float4*)(xb + (size_t)ic * NPIX))[pv];
    }
    __syncthreads();

    u64 acc[6][8];
#pragma unroll
    for (int p = 0; p < 6; p++)
#pragma unroll
        for (int j = 0; j < 8; j++) acc[p][j] = 0ull;

    const int ocb = ty * 12;
#pragma unroll 4
    for (int k = 0; k < 64; k++) {
        // 6 oc-pairs: reinterpret shared weight row (ocb*4 = 48*ty, 16B aligned)
        const ulonglong2* wp = (const ulonglong2*)(ws + k * QKVC + ocb);
        ulonglong2 wA = wp[0], wB = wp[1], wC = wp[2];
        u64 wr[6] = {wA.x, wA.y, wB.x, wB.y, wC.x, wC.y};
        u64 xd[8];
#pragma unroll
        for (int j = 0; j < 8; j++) {
            float xv = xs[k * 128 + tx + 16 * j];
            xd[j] = pk2(xv, xv);
        }
#pragma unroll
        for (int p = 0; p < 6; p++)
#pragma unroll
            for (int j = 0; j < 8; j++)
                fma2(acc[p][j], wr[p], xd[j], acc[p][j]);
    }

    float* ob = g_mid + (size_t)b * QKVC * NPIX + n0;
#pragma unroll
    for (int p = 0; p < 6; p++)
#pragma unroll
        for (int j = 0; j < 8; j++) {
            float2 r = upk2(acc[p][j]);
            ob[(size_t)(ocb + 2 * p) * NPIX + tx + 16 * j]     = r.x;
            ob[(size_t)(ocb + 2 * p + 1) * NPIX + tx + 16 * j] = r.y;
        }
}

// ---------------- kernel 2: depthwise 3x3 conv + fused sq-norm --------------
// grid (8, 16, B*192), block (32, 8): 32x16 pixel tile, 2 pixels/thread.
__global__ void k_dw(const float* __restrict__ wdw) {
    const int bc = blockIdx.z;           // b*192 + c
    const int c  = bc % QKVC;
    const int b  = bc / QKVC;
    const int x0 = blockIdx.x * 32, y0 = blockIdx.y * 16;

    __shared__ float tile[18][34];
    const float* in = g_mid + (size_t)bc * NPIX;
    const int tid = threadIdx.y * 32 + threadIdx.x;

    for (int idx = tid; idx < 612; idx += 256) {
        int yy = idx / 34, xx = idx % 34;
        int gy = y0 + yy - 1, gx = x0 + xx - 1;
        tile[yy][xx] = (gy >= 0 && gy < HH && gx >= 0 && gx < WW)
                           ? in[gy * WW + gx] : 0.f;
    }
    __syncthreads();

    float w[9];
#pragma unroll
    for (int t = 0; t < 9; t++) w[t] = wdw[c * 9 + t];

    float sq = 0.f;
    float* outp = g_qkv + (size_t)bc * NPIX + x0 + threadIdx.x;
#pragma unroll
    for (int half = 0; half < 2; half++) {
        const int ly = threadIdx.y + half * 8;
        float a = 0.f;
#pragma unroll
        for (int ky = 0; ky < 3; ky++)
#pragma unroll
            for (int kx = 0; kx < 3; kx++)
                a = fmaf(w[ky * 3 + kx], tile[ly + ky][threadIdx.x + kx], a);
        outp[(size_t)(y0 + ly) * WW] = a;
        sq = fmaf(a, a, sq);
    }

    if (c < 2 * DIM) {  // q or k channel: accumulate sum of squares
        float s = sq;
#pragma unroll
        for (int o = 16; o; o >>= 1) s += __shfl_down_sync(0xffffffffu, s, o);
        __shared__ float red[8];
        if (threadIdx.x == 0) red[threadIdx.y] = s;
        __syncthreads();
        if (tid == 0) {
            float tot = 0.f;
#pragma unroll
            for (int wv = 0; wv < 8; wv++) tot += red[wv];
            atomicAdd(&g_sqn[b * 2 * DIM + c], tot);
        }
    }
}

// ---------------- kernel 3: Gram matrix G = q @ k^T (unnormalized) ----------
// grid (64 chunks, B*HEADS). Each block: 1024 pixels, full 32x32 output tile.
__global__ __launch_bounds__(256) void k_gram() {
    __shared__ float qs[32][132];
    __shared__ float ks[32][132];

    const int bh = blockIdx.y;
    const int b = bh >> 1, h = bh & 1;
    const long n0 = (long)blockIdx.x * 1024;
    const float* qg = g_qkv + ((size_t)b * QKVC + h * CH) * NPIX + n0;
    const float* kg = g_qkv + ((size_t)b * QKVC + DIM + h * CH) * NPIX + n0;
    const int tid = threadIdx.x;
    const int i0 = (tid >> 4) * 2;
    const int j0 = (tid & 15) * 2;

    float a00 = 0.f, a01 = 0.f, a10 = 0.f, a11 = 0.f;
    for (int s = 0; s < 8; s++) {
        __syncthreads();
        for (int idx = tid; idx < 32 * 32; idx += 256) {
            int r = idx >> 5, pv = idx & 31;
            ((float4*)qs[r])[pv] = ((const float4*)(qg + (size_t)r * NPIX + s * 128))[pv];
            ((float4*)ks[r])[pv] = ((const float4*)(kg + (size_t)r * NPIX + s * 128))[pv];
        }
        __syncthreads();
#pragma unroll 8
        for (int p = 0; p < 128; p += 4) {
            float4 qa = *(float4*)&qs[i0][p];
            float4 qb = *(float4*)&qs[i0 + 1][p];
            float4 ka = *(float4*)&ks[j0][p];
            float4 kb = *(float4*)&ks[j0 + 1][p];
            a00 = fmaf(qa.x, ka.x, fmaf(qa.y, ka.y, fmaf(qa.z, ka.z, fmaf(qa.w, ka.w, a00))));
            a01 = fmaf(qa.x, kb.x, fmaf(qa.y, kb.y, fmaf(qa.z, kb.z, fmaf(qa.w, kb.w, a01))));
            a10 = fmaf(qb.x, ka.x, fmaf(qb.y, ka.y, fmaf(qb.z, ka.z, fmaf(qb.w, ka.w, a10))));
            a11 = fmaf(qb.x, kb.x, fmaf(qb.y, kb.y, fmaf(qb.z, kb.z, fmaf(qb.w, kb.w, a11))));
        }
    }
    float* G = g_gram + bh * CH * CH;
    atomicAdd(&G[i0 * CH + j0],           a00);
    atomicAdd(&G[i0 * CH + j0 + 1],       a01);
    atomicAdd(&G[(i0 + 1) * CH + j0],     a10);
    atomicAdd(&G[(i0 + 1) * CH + j0 + 1], a11);
}

// ---------------- kernel 4: normalize, triple top-k softmax, combine --------
__global__ void k_comb(const float* __restrict__ temp, const float* __restrict__ a1,
                       const float* __restrict__ a2, const float* __restrict__ a3) {
    const int bh = blockIdx.x;
    const int b = bh >> 1, h = bh & 1;
    const int i = threadIdx.x;

    __shared__ float nks[CH];
    float nq = fmaxf(sqrtf(g_sqn[b * 2 * DIM + h * CH + i]), 1e-12f);
    float nk = fmaxf(sqrtf(g_sqn[b * 2 * DIM + DIM + h * CH + i]), 1e-12f);
    nks[i] = nk;
    __syncthreads();

    const float t = temp[h];
    float v[CH];
#pragma unroll
    for (int j = 0; j < CH; j++)
        v[j] = g_gram[bh * CH * CH + i * CH + j] / nq * t / nks[j];

    int rank[CH];
#pragma unroll
    for (int j = 0; j < CH; j++) {
        int r = 0;
        float vj = v[j];
#pragma unroll
        for (int l = 0; l < CH; l++)
            r += (v[l] > vj) || (v[l] == vj && l < j);
        rank[j] = r;
    }

    float mx = -1e30f;
#pragma unroll
    for (int j = 0; j < CH; j++) mx = fmaxf(mx, v[j]);

    float e[CH], s16 = 0.f, s21 = 0.f, s24 = 0.f;
#pragma unroll
    for (int j = 0; j < CH; j++) {
        float ev = expf(v[j] - mx);
        e[j] = ev;
        if (rank[j] < 16) s16 += ev;
        if (rank[j] < 21) s21 += ev;
        if (rank[j] < 24) s24 += ev;
    }
    const float w1 = a1[0] / s16, w2 = a2[0] / s21, w3 = a3[0] / s24;
#pragma unroll
    for (int j = 0; j < CH; j++) {
        float coef = (rank[j] < 16 ? w1 : 0.f) + (rank[j] < 21 ? w2 : 0.f)
                   + (rank[j] < 24 ? w3 : 0.f);
        g_A[bh * CH * CH + i * CH + j] = e[j] * coef;
    }
}

// ---------------- kernel 5: M[b] = W_proj @ blockdiag(A[b,0], A[b,1]) -------
__global__ void k_buildM(const float* __restrict__ wproj) {
    const int b = blockIdx.x;
    __shared__ float As[HEADS * CH * CH];  // 2048
    __shared__ float Ws[DIM * DIM];        // 4096
    const int tid = threadIdx.x;           // 128 threads
    for (int idx = tid; idx < HEADS * CH * CH; idx += 128) As[idx] = g_A[b * HEADS * CH * CH + idx];
    for (int idx = tid; idx < DIM * DIM; idx += 128)       Ws[idx] = wproj[idx];
    __syncthreads();

#pragma unroll
    for (int m = 0; m < 32; m++) {
        int idx = tid + 128 * m;
        int o = idx >> 6, ci = idx & 63;
        int h = ci >> 5, cj = ci & 31;
        float s = 0.f;
#pragma unroll
        for (int cp = 0; cp < CH; cp++)
            s = fmaf(Ws[o * DIM + h * CH + cp], As[h * CH * CH + cp * CH + cj], s);
        g_M[b * DIM * DIM + idx] = s;
    }
}

// ---------------- kernel 6: out = M[b] @ v, f32x2 packed over pixel pairs ---
// Block: 256 pixels, 64 oc. 16x16 threads; thread: 4 oc x 8 pixel-pairs.
__global__ __launch_bounds__(256) void k_out(float* __restrict__ out) {
    extern __shared__ float sm[];
    float* ms = sm;             // [64][64]  ms[ci][o]  (transposed M)
    float* vs = sm + DIM * DIM; // [64][256] vs[ci][px]

    const int b = blockIdx.y;
    const long n0 = (long)blockIdx.x * 256;
    const int tx = threadIdx.x, ty = threadIdx.y;
    const int tid = ty * 16 + tx;

    const float* Mb = g_M + b * DIM * DIM;
    for (int idx = tid; idx < DIM * DIM; idx += 256) {
        int o = idx >> 6, ci = idx & 63;
        ms[ci * DIM + o] = Mb[idx];
    }
    const float* vg = g_qkv + ((size_t)b * QKVC + 2 * DIM) * NPIX + n0;
    for (int idx = tid; idx < 64 * 64; idx += 256) {
        int ci = idx >> 6, pv = idx & 63;
        ((float4*)&vs[ci * 256])[pv] = ((const float4*)(vg + (size_t)ci * NPIX))[pv];
    }
    __syncthreads();

    u64 acc[4][8];
#pragma unroll
    for (int i = 0; i < 4; i++)
#pragma unroll
        for (int j = 0; j < 8; j++) acc[i][j] = 0ull;

    const int ob4 = ty * 4;
#pragma unroll 4
    for (int ci = 0; ci < 64; ci++) {
        float4 w = *(float4*)&ms[ci * DIM + ob4];
        u64 wd[4] = {pk2(w.x, w.x), pk2(w.y, w.y), pk2(w.z, w.z), pk2(w.w, w.w)};
        // 8 natural pixel pairs per thread: pair j covers pixels 2*(tx+16j), +1
        u64 xp[8];
#pragma unroll
        for (int j = 0; j < 8; j++)
            xp[j] = *(const u64*)&vs[ci * 256 + 2 * (tx + 16 * j)];
#pragma unroll
        for (int i = 0; i < 4; i++)
#pragma unroll
            for (int j = 0; j < 8; j++)
                fma2(acc[i][j], wd[i], xp[j], acc[i][j]);
    }

    float* ob = out + (size_t)b * DIM * NPIX + n0;
#pragma unroll
    for (int i = 0; i < 4; i++)
#pragma unroll
        for (int j = 0; j < 8; j++) {
            float2 r = upk2(acc[i][j]);
            *(float2*)&ob[(size_t)(ob4 + i) * NPIX + 2 * (tx + 16 * j)] = r;
        }
}

// ---------------- launcher ---------------------------------------------------
extern "C" void kernel_launch(void* const* d_in, const int* in_sizes, int n_in,
                              void* d_out, int out_size) {
    const float* x     = (const float*)d_in[0];
    const float* wqkv  = (const float*)d_in[1];
    const float* wdw   = (const float*)d_in[2];
    const float* wproj = (const float*)d_in[3];
    const float* temp  = (const float*)d_in[4];
    const float* a1    = (const float*)d_in[5];
    const float* a2    = (const float*)d_in[6];
    const float* a3    = (const float*)d_in[7];
    float* out = (float*)d_out;

    cudaFuncSetAttribute(k_conv1, cudaFuncAttributeMaxDynamicSharedMemorySize, 81920);
    cudaFuncSetAttribute(k_out,   cudaFuncAttributeMaxDynamicSharedMemorySize, 81920);

    k_zero<<<64, 256>>>();
    k_conv1<<<dim3(512, 8), dim3(16, 16), 81920>>>(x, wqkv);
    k_dw<<<dim3(8, 16, B * QKVC), dim3(32, 8)>>>(wdw);
    k_gram<<<dim3(64, 16), 256>>>();
    k_comb<<<16, 32>>>(temp, a1, a2, a3);
    k_buildM<<<8, 128>>>(wproj);
    k_out<<<dim3(256, 8), dim3(16, 16), 81920>>>(out);
}